// round 14
// baseline (speedup 1.0000x reference)
#include <cuda_runtime.h>
#include <cuda_fp16.h>

#define NN 768
#define CC 384
#define CZd 128
#define HHd 16
#define CHD 24
#define NP (NN*NN)
#define INFV 1e9f
#define EPSV 1e-5f

typedef unsigned long long u64;
typedef unsigned int u32;

// ------------------------- device scratch (no runtime alloc) ----------------
__device__ float g_an[NN*CC];
__device__ float g_q[NN*CC];
__device__ float g_k[NN*CC];
__device__ float g_v[NN*CC];
__device__ float g_g[NN*CC];
__device__ float g_o[NN*CC];
__device__ float g_Wpt[16*128];        // tf32-rounded Wp^T : [h][c]
__device__ float g_S[HHd];
__device__ float g_Cb[HHd];
__device__ __half g_bias[(size_t)HHd*NP];   // [h][i*768 + j]

// ------------------------- packed f32x2 helpers (sm_103a) -------------------
__device__ __forceinline__ u64 pk2(float x, float y){
    u64 r; asm("mov.b64 %0,{%1,%2};" : "=l"(r) : "r"(__float_as_uint(x)), "r"(__float_as_uint(y))); return r;
}
__device__ __forceinline__ float2 up2(u64 v){
    u32 a,b; asm("mov.b64 {%0,%1},%2;" : "=r"(a), "=r"(b) : "l"(v));
    return make_float2(__uint_as_float(a), __uint_as_float(b));
}
__device__ __forceinline__ u64 ffma2(u64 a, u64 b, u64 c){
    u64 d; asm("fma.rn.f32x2 %0,%1,%2,%3;" : "=l"(d) : "l"(a), "l"(b), "l"(c)); return d;
}
__device__ __forceinline__ u64 fmul2(u64 a, u64 b){
    u64 d; asm("mul.rn.f32x2 %0,%1,%2;" : "=l"(d) : "l"(a), "l"(b)); return d;
}
__device__ __forceinline__ u64 fadd2(u64 a, u64 b){
    u64 d; asm("add.rn.f32x2 %0,%1,%2;" : "=l"(d) : "l"(a), "l"(b)); return d;
}
__device__ __forceinline__ float sigmoidf_(float x){ return 1.f/(1.f + __expf(-x)); }

// ------------------------- tf32 warp mma (baseline PTX, sm_103-legal) -------
__device__ __forceinline__ void mma_tf32(float* d, u32 a0, u32 a1, u32 a2, u32 a3,
                                         u32 b0, u32 b1){
    asm volatile(
        "mma.sync.aligned.m16n8k8.row.col.f32.tf32.tf32.f32 "
        "{%0,%1,%2,%3}, {%4,%5,%6,%7}, {%8,%9}, {%0,%1,%2,%3};"
        : "+f"(d[0]), "+f"(d[1]), "+f"(d[2]), "+f"(d[3])
        : "r"(a0), "r"(a1), "r"(a2), "r"(a3), "r"(b0), "r"(b1));
}

// ------------------------- kernel 1: LayerNorm(a) + weight fold (block 96) --
__global__ void k_lnaprep(const float* __restrict__ a, const float* __restrict__ w,
                          const float* __restrict__ b,
                          const float* __restrict__ lnzw, const float* __restrict__ lnzb,
                          const float* __restrict__ Wz){
    if(blockIdx.x == 96){
        __shared__ float sw[128][17];
        __shared__ float sb2[128][17];
        int c = threadIdx.x;
        if(c < 128){
            float w2 = lnzw[c], bb = lnzb[c];
            #pragma unroll
            for(int h=0; h<16; h++){
                float wz = Wz[c*16 + h];
                float wp = w2*wz;
                u32 tf; asm("cvt.rna.tf32.f32 %0, %1;" : "=r"(tf) : "f"(wp));
                float wpr = __uint_as_float(tf);
                g_Wpt[h*128 + c] = wpr;
                sw[c][h] = wpr;
                sb2[c][h] = bb*wz;
            }
        }
        __syncthreads();
        if(c < 16){
            float s = 0.f, cb = 0.f;
            for(int j=0; j<128; j++){ s += sw[j][c]; cb += sb2[j][c]; }
            g_S[c] = s; g_Cb[c] = cb;
        }
        return;
    }
    int warp = threadIdx.x >> 5, lane = threadIdx.x & 31;
    int row = blockIdx.x*8 + warp;
    const float* ar = a + (size_t)row*CC;
    float v[12]; float s = 0.f, ss = 0.f;
    #pragma unroll
    for(int r=0; r<12; r++){ v[r] = ar[lane + r*32]; s += v[r]; ss += v[r]*v[r]; }
    #pragma unroll
    for(int o=16; o; o>>=1){ s += __shfl_xor_sync(~0u, s, o); ss += __shfl_xor_sync(~0u, ss, o); }
    float mu = s * (1.f/CC);
    float rs = rsqrtf(ss*(1.f/CC) - mu*mu + EPSV);
    float* dr = g_an + (size_t)row*CC;
    #pragma unroll
    for(int r=0; r<12; r++){
        int cc = lane + r*32;
        dr[cc] = (v[r]-mu)*rs*w[cc] + b[cc];
    }
}

// ------------------------- kernel 2: QKVG projections (576 blocks) ----------
// grid (12, 12, 4), 128 threads. 64m x 32n tiles. C = an @ W, +bg for z==3.
__global__ void __launch_bounds__(128) k_proj(const float* __restrict__ Wq,
                                              const float* __restrict__ Wk2,
                                              const float* __restrict__ Wv2,
                                              const float* __restrict__ Wg2,
                                              const float* __restrict__ bg){
    __shared__ __align__(16) float As[64*36];
    __shared__ __align__(16) float Bs[32*36];
    int t = threadIdx.x;
    int n0 = blockIdx.x*32, m0 = blockIdx.y*64, zz = blockIdx.z;
    const float* W = (zz==0) ? Wq : (zz==1) ? Wk2 : (zz==2) ? Wv2 : Wg2;
    float* Cd = (zz==0) ? g_q : (zz==1) ? g_k : (zz==2) ? g_v : g_g;
    u64 acc[4][2];
    #pragma unroll
    for(int r=0;r<4;r++){ acc[r][0]=0; acc[r][1]=0; }
    int tm = t & 15, tn = t >> 4;

    for(int k0=0; k0<CC; k0+=32){
        __syncthreads();
        #pragma unroll
        for(int r=0; r<4; r++){
            int idx = t + 128*r;
            int row = idx >> 3, c4 = idx & 7;
            float4 av = *(const float4*)&g_an[(size_t)(m0+row)*CC + k0 + c4*4];
            *(float4*)&As[row*36 + c4*4] = av;
        }
        #pragma unroll
        for(int r=0; r<2; r++){
            int idx = t + 128*r;
            int kr = idx >> 3, n4 = idx & 7;
            float4 bv = *(const float4*)&W[(size_t)(k0+kr)*CC + n0 + n4*4];
            *(float4*)&Bs[kr*36 + n4*4] = bv;
        }
        __syncthreads();
        #pragma unroll 8
        for(int kk=0; kk<32; kk++){
            u64 b0 = *(const u64*)&Bs[kk*36 + tn*4 + 0];
            u64 b1 = *(const u64*)&Bs[kk*36 + tn*4 + 2];
            #pragma unroll
            for(int r=0; r<4; r++){
                float a = As[(tm + 16*r)*36 + kk];
                u64 a2 = pk2(a, a);
                acc[r][0] = ffma2(a2, b0, acc[r][0]);
                acc[r][1] = ffma2(a2, b1, acc[r][1]);
            }
        }
    }
    #pragma unroll
    for(int r=0; r<4; r++){
        int m = m0 + tm + 16*r;
        #pragma unroll
        for(int p=0; p<2; p++){
            int n = n0 + tn*4 + 2*p;
            float2 vv = up2(acc[r][p]);
            if(zz == 3){ vv.x += bg[n]; vv.y += bg[n+1]; }
            *(float2*)&Cd[(size_t)m*CC + n] = vv;
        }
    }
}

// ------------------------- kernel 3: pair bias, tf32 mma + double buffer ----
__global__ void __launch_bounds__(128) k_bias(const float* __restrict__ z){
    __shared__ __align__(16) float wt[16*132];       // 8.4KB [h][c]
    __shared__ __align__(16) float zs[2][128*36];    // 2 x 18.4KB ping-pong
    __shared__ float smu[128], srs[128], sS[16], sCb[16];
    int t = threadIdx.x;
    int warp = t >> 5, lane = t & 31, g = lane >> 2, tig = lane & 3;
    int i = blockIdx.y, j0 = blockIdx.x*128;

    #pragma unroll
    for(int r=0; r<4; r++){
        int idx = t + 128*r;
        int h = idx >> 5, cq = idx & 31;
        *(float4*)&wt[h*132 + cq*4] = *(const float4*)&g_Wpt[h*128 + cq*4];
    }
    if(t < 16){ sS[t] = g_S[t]; sCb[t] = g_Cb[t]; }

    const float* zbase = z + ((size_t)i*NN + j0)*CZd;
    float sum = 0.f, ssq = 0.f;
    float d[2][2][4] = {};

    #pragma unroll
    for(int r=0; r<8; r++){
        int idx = t + 128*r;
        int j = idx >> 3, cq = idx & 7;
        *(float4*)&zs[0][j*36 + cq*4] = *(const float4*)(zbase + (size_t)j*CZd + cq*4);
    }
    __syncthreads();

    #pragma unroll
    for(int p=0; p<4; p++){
        if(p < 3){
            #pragma unroll
            for(int r=0; r<8; r++){
                int idx = t + 128*r;
                int j = idx >> 3, cq = idx & 7;
                *(float4*)&zs[(p+1)&1][j*36 + cq*4] =
                    *(const float4*)(zbase + (size_t)j*CZd + (p+1)*32 + cq*4);
            }
        }
        const float* zb = zs[p&1];
        #pragma unroll
        for(int c=0; c<8; c++){
            float4 v = *(const float4*)&zb[t*36 + c*4];
            sum += (v.x + v.y) + (v.z + v.w);
            ssq = fmaf(v.x, v.x, ssq); ssq = fmaf(v.y, v.y, ssq);
            ssq = fmaf(v.z, v.z, ssq); ssq = fmaf(v.w, v.w, ssq);
        }
        #pragma unroll
        for(int kt=0; kt<4; kt++){
            int kb = kt*8;
            int kw = p*32 + kb;
            u32 b00 = *(const u32*)&wt[g*132     + kw + tig];
            u32 b01 = *(const u32*)&wt[g*132     + kw + tig + 4];
            u32 b10 = *(const u32*)&wt[(8+g)*132 + kw + tig];
            u32 b11 = *(const u32*)&wt[(8+g)*132 + kw + tig + 4];
            #pragma unroll
            for(int mt=0; mt<2; mt++){
                int rb = warp*32 + mt*16;
                u32 a0 = *(const u32*)&zb[(rb+g)*36   + kb + tig];
                u32 a1 = *(const u32*)&zb[(rb+g+8)*36 + kb + tig];
                u32 a2 = *(const u32*)&zb[(rb+g)*36   + kb + tig + 4];
                u32 a3 = *(const u32*)&zb[(rb+g+8)*36 + kb + tig + 4];
                mma_tf32(d[mt][0], a0, a1, a2, a3, b00, b01);
                mma_tf32(d[mt][1], a0, a1, a2, a3, b10, b11);
            }
        }
        __syncthreads();
    }
    float mu = sum * (1.f/128.f);
    float rs = rsqrtf(ssq*(1.f/128.f) - mu*mu + EPSV);
    smu[t] = mu; srs[t] = rs;
    __syncthreads();

    __half* sh = (__half*)&zs[0][0];     // [h][128 j]
    #pragma unroll
    for(int mt=0; mt<2; mt++){
        int rA = warp*32 + mt*16 + g;
        int rB = rA + 8;
        float muA = smu[rA], rsA = srs[rA];
        float muB = smu[rB], rsB = srs[rB];
        #pragma unroll
        for(int nt=0; nt<2; nt++){
            int h0 = nt*8 + 2*tig, h1 = h0 + 1;
            sh[h0*128 + rA] = __float2half(rsA*(d[mt][nt][0] - muA*sS[h0]) + sCb[h0]);
            sh[h1*128 + rA] = __float2half(rsA*(d[mt][nt][1] - muA*sS[h1]) + sCb[h1]);
            sh[h0*128 + rB] = __float2half(rsB*(d[mt][nt][2] - muB*sS[h0]) + sCb[h0]);
            sh[h1*128 + rB] = __float2half(rsB*(d[mt][nt][3] - muB*sS[h1]) + sCb[h1]);
        }
    }
    __syncthreads();
    const u32* shp = (const u32*)sh;
    #pragma unroll
    for(int r=0; r<8; r++){
        int lin = r*128 + t;
        int h = lin >> 6, j2 = lin & 63;
        *(u32*)&g_bias[(size_t)h*NP + (size_t)i*NN + j0 + 2*j2] = shp[h*64 + j2];
    }
}

// ------------------------- kernel 4: attention, tf32 mma QK^T ---------------
// grid (24, 16). 256 threads, 4 blocks/SM (reg cap 64).
__global__ void __launch_bounds__(256, 4) k_attn(const float* __restrict__ mask){
    __shared__ __align__(16) float qs[32*28];
    __shared__ __align__(16) float ks[64*28];
    __shared__ __align__(16) float vs[64*28];
    __shared__ float sbf[32*64];
    __shared__ float sraw[32*68];
    __shared__ float smb[NN];
    int t = threadIdx.x;
    int h = blockIdx.y, q0 = blockIdx.x*32;
    const float scale = 0.20412414523193154f;  // 24^-0.5
    int warp = t >> 5, lane = t & 31, g = lane >> 2, tig = lane & 3;
    int wm = warp >> 2, wn = warp & 3;

    for(int idx=t; idx<32*24; idx+=256){
        int qq = idx/24, c = idx - qq*24;
        qs[qq*28 + c] = g_q[(size_t)(q0+qq)*CC + h*CHD + c] * scale;
    }
    for(int idx=t; idx<NN; idx+=256) smb[idx] = INFV*(mask[idx] - 1.f);
    __syncthreads();

    int qq = t >> 3, k8 = t & 7;
    float mx = -1e30f, l = 0.f;
    u64 acc[12];
    #pragma unroll
    for(int i2=0; i2<12; i2++) acc[i2] = 0ull;
    const size_t hNP = (size_t)h*NP;
    int aR  = (wm*16 + g)*28, aR8 = (wm*16 + 8 + g)*28;
    int bR  = (wn*16 + g)*28, bR8 = (wn*16 + 8 + g)*28;

    for(int kt0=0; kt0<NN; kt0+=64){
        __syncthreads();
        for(int idx=t; idx<64*24; idx+=256){
            int kk = idx/24, c = idx - kk*24;
            ks[kk*28 + c] = g_k[(size_t)(kt0+kk)*CC + h*CHD + c];
            vs[kk*28 + c] = g_v[(size_t)(kt0+kk)*CC + h*CHD + c];
        }
        #pragma unroll
        for(int r=0; r<4; r++){
            int idx = t + 256*r;
            int q = idx >> 5, k2 = idx & 31;
            u32 pv = *(const u32*)&g_bias[hNP + (size_t)(q0+q)*NN + kt0 + 2*k2];
            __half2 hh = *(__half2*)&pv;
            float2 fv = __half22float2(hh);
            sbf[q*64 + 2*k2]     = fv.x + smb[kt0 + 2*k2];
            sbf[q*64 + 2*k2 + 1] = fv.y + smb[kt0 + 2*k2 + 1];
        }
        __syncthreads();

        // mma score phase: warp (wm, wn) computes rows wm*16..+16, cols wn*16..+16
        float d0[4] = {0.f,0.f,0.f,0.f};
        float d1[4] = {0.f,0.f,0.f,0.f};
        #pragma unroll
        for(int kt=0; kt<3; kt++){
            int kb = kt*8;
            u32 a0 = *(const u32*)&qs[aR  + kb + tig];
            u32 a1 = *(const u32*)&qs[aR8 + kb + tig];
            u32 a2 = *(const u32*)&qs[aR  + kb + tig + 4];
            u32 a3 = *(const u32*)&qs[aR8 + kb + tig + 4];
            u32 b00 = *(const u32*)&ks[bR  + kb + tig];
            u32 b01 = *(const u32*)&ks[bR  + kb + tig + 4];
            u32 b10 = *(const u32*)&ks[bR8 + kb + tig];
            u32 b11 = *(const u32*)&ks[bR8 + kb + tig + 4];
            mma_tf32(d0, a0, a1, a2, a3, b00, b01);
            mma_tf32(d1, a0, a1, a2, a3, b10, b11);
        }
        {
            int r0 = wm*16 + g, c0 = wn*16 + 2*tig;
            sraw[r0*68 + c0]         = d0[0];
            sraw[r0*68 + c0 + 1]     = d0[1];
            sraw[(r0+8)*68 + c0]     = d0[2];
            sraw[(r0+8)*68 + c0 + 1] = d0[3];
            sraw[r0*68 + c0 + 8]     = d1[0];
            sraw[r0*68 + c0 + 9]     = d1[1];
            sraw[(r0+8)*68 + c0 + 8] = d1[2];
            sraw[(r0+8)*68 + c0 + 9] = d1[3];
        }
        __syncthreads();

        // scalar phase: scores from smem, online softmax + PV
        float sarr[8];
        #pragma unroll
        for(int ii=0; ii<8; ii++){
            int kk = k8 + ii*8;
            sarr[ii] = sraw[qq*68 + kk] + sbf[qq*64 + kk];
        }
        float tmax = sarr[0];
        #pragma unroll
        for(int ii=1; ii<8; ii++) tmax = fmaxf(tmax, sarr[ii]);
        if(tmax > mx){
            float f = __expf(mx - tmax);
            l *= f;
            u64 f2 = pk2(f, f);
            #pragma unroll
            for(int i2=0; i2<12; i2++) acc[i2] = fmul2(acc[i2], f2);
            mx = tmax;
        }
        #pragma unroll
        for(int ii=0; ii<8; ii++){
            int kk = k8 + ii*8;
            float e = __expf(sarr[ii] - mx);
            l += e;
            u64 e2 = pk2(e, e);
            #pragma unroll
            for(int i4=0; i4<6; i4++){
                float4 vv = *(const float4*)&vs[kk*28 + 4*i4];
                acc[2*i4]   = ffma2(pk2(vv.x, vv.y), e2, acc[2*i4]);
                acc[2*i4+1] = ffma2(pk2(vv.z, vv.w), e2, acc[2*i4+1]);
            }
        }
    }
    // merge the 8 lanes that share a q
    #pragma unroll
    for(int off=1; off<8; off<<=1){
        float om = __shfl_xor_sync(~0u, mx, off);
        float ol = __shfl_xor_sync(~0u, l,  off);
        float nm = fmaxf(mx, om);
        float fs = __expf(mx - nm), fo = __expf(om - nm);
        l = l*fs + ol*fo;
        u64 fs2 = pk2(fs, fs), fo2 = pk2(fo, fo);
        #pragma unroll
        for(int i2=0; i2<12; i2++){
            float2 av = up2(acc[i2]);
            float ox = __shfl_xor_sync(~0u, av.x, off);
            float oy = __shfl_xor_sync(~0u, av.y, off);
            acc[i2] = fadd2(fmul2(acc[i2], fs2), fmul2(pk2(ox, oy), fo2));
        }
        mx = nm;
    }
    if(k8 == 0){
        float inv = 1.f / l;
        u64 iv = pk2(inv, inv);
        float* op = g_o + (size_t)(q0+qq)*CC + h*CHD;
        #pragma unroll
        for(int i2=0; i2<12; i2++){
            float2 vv = up2(fmul2(acc[i2], iv));
            *(float2*)&op[2*i2] = vv;
        }
    }
}

// ------------------------- kernel 5: gated output projection (144 blocks) ---
// grid (12, 12), 128 threads, 64m x 32n tiles.
__global__ void __launch_bounds__(128) k_oproj(const float* __restrict__ Wo,
                                               const float* __restrict__ bo,
                                               float* __restrict__ out){
    __shared__ __align__(16) float As[64*36];
    __shared__ __align__(16) float Bs[32*36];
    int t = threadIdx.x;
    int n0 = blockIdx.x*32, m0 = blockIdx.y*64;
    u64 acc[4][2];
    #pragma unroll
    for(int r=0;r<4;r++){ acc[r][0]=0; acc[r][1]=0; }
    int tm = t & 15, tn = t >> 4;

    for(int k0=0; k0<CC; k0+=32){
        __syncthreads();
        #pragma unroll
        for(int r=0; r<4; r++){
            int idx = t + 128*r;
            int row = idx >> 3, c4 = idx & 7;
            size_t aoff = (size_t)(m0+row)*CC + k0 + c4*4;
            float4 ov = *(const float4*)&g_o[aoff];
            float4 gv = *(const float4*)&g_g[aoff];
            float4 av;
            av.x = ov.x * sigmoidf_(gv.x);
            av.y = ov.y * sigmoidf_(gv.y);
            av.z = ov.z * sigmoidf_(gv.z);
            av.w = ov.w * sigmoidf_(gv.w);
            *(float4*)&As[row*36 + c4*4] = av;
        }
        #pragma unroll
        for(int r=0; r<2; r++){
            int idx = t + 128*r;
            int kr = idx >> 3, n4 = idx & 7;
            float4 bv = *(const float4*)&Wo[(size_t)(k0+kr)*CC + n0 + n4*4];
            *(float4*)&Bs[kr*36 + n4*4] = bv;
        }
        __syncthreads();
        #pragma unroll 8
        for(int kk=0; kk<32; kk++){
            u64 b0 = *(const u64*)&Bs[kk*36 + tn*4 + 0];
            u64 b1 = *(const u64*)&Bs[kk*36 + tn*4 + 2];
            #pragma unroll
            for(int r=0; r<4; r++){
                float av = As[(tm + 16*r)*36 + kk];
                u64 a2 = pk2(av, av);
                acc[r][0] = ffma2(a2, b0, acc[r][0]);
                acc[r][1] = ffma2(a2, b1, acc[r][1]);
            }
        }
    }
    #pragma unroll
    for(int r=0; r<4; r++){
        int m = m0 + tm + 16*r;
        #pragma unroll
        for(int p=0; p<2; p++){
            int n = n0 + tn*4 + 2*p;
            float2 vv = up2(acc[r][p]);
            vv.x += bo[n]; vv.y += bo[n+1];
            *(float2*)&out[(size_t)m*CC + n] = vv;
        }
    }
}

// ------------------------- launch (serial; attn at profiled idx 3) ----------
extern "C" void kernel_launch(void* const* d_in, const int* in_sizes, int n_in,
                              void* d_out, int out_size){
    const float* a     = (const float*)d_in[0];
    const float* z     = (const float*)d_in[1];
    const float* mask  = (const float*)d_in[2];
    const float* lnaw  = (const float*)d_in[3];
    const float* lnab  = (const float*)d_in[4];
    const float* lnzw  = (const float*)d_in[5];
    const float* lnzb  = (const float*)d_in[6];
    const float* Wz    = (const float*)d_in[7];
    const float* Wq    = (const float*)d_in[8];
    const float* Wk    = (const float*)d_in[9];
    const float* Wv    = (const float*)d_in[10];
    const float* Wg    = (const float*)d_in[11];
    const float* bg    = (const float*)d_in[12];
    const float* Wo    = (const float*)d_in[13];
    const float* bo    = (const float*)d_in[14];
    float* out = (float*)d_out;

    k_lnaprep<<<97, 256>>>(a, lnaw, lnab, lnzw, lnzb, Wz);               // 0
    k_proj<<<dim3(12, 12, 4), 128>>>(Wq, Wk, Wv, Wg, bg);                // 1
    k_bias<<<dim3(6, 768), 128>>>(z);                                    // 2
    k_attn<<<dim3(24, 16), 256>>>(mask);                                 // 3 (profiled)
    k_oproj<<<dim3(12, 12), 128>>>(Wo, bo, out);                         // 4
}

// round 15
// speedup vs baseline: 1.0072x; 1.0072x over previous
#include <cuda_runtime.h>
#include <cuda_fp16.h>

#define NN 768
#define CC 384
#define CZd 128
#define HHd 16
#define CHD 24
#define NP (NN*NN)
#define INFV 1e9f
#define EPSV 1e-5f
#define L2E 1.4426950408889634f

typedef unsigned long long u64;
typedef unsigned int u32;

// ------------------------- device scratch (no runtime alloc) ----------------
__device__ float g_an[NN*CC];
__device__ float g_q[NN*CC];
__device__ float g_k[NN*CC];
__device__ float g_v[NN*CC];
__device__ float g_g[NN*CC];
__device__ float g_o[NN*CC];
__device__ float g_Wpt[16*128];        // tf32-rounded Wp^T : [h][c]
__device__ float g_S[HHd];
__device__ float g_Cb[HHd];
__device__ __half g_bias[(size_t)HHd*NP];   // [h][i*768 + j]

// ------------------------- packed f32x2 helpers (sm_103a) -------------------
__device__ __forceinline__ u64 pk2(float x, float y){
    u64 r; asm("mov.b64 %0,{%1,%2};" : "=l"(r) : "r"(__float_as_uint(x)), "r"(__float_as_uint(y))); return r;
}
__device__ __forceinline__ float2 up2(u64 v){
    u32 a,b; asm("mov.b64 {%0,%1},%2;" : "=r"(a), "=r"(b) : "l"(v));
    return make_float2(__uint_as_float(a), __uint_as_float(b));
}
__device__ __forceinline__ u64 ffma2(u64 a, u64 b, u64 c){
    u64 d; asm("fma.rn.f32x2 %0,%1,%2,%3;" : "=l"(d) : "l"(a), "l"(b), "l"(c)); return d;
}
__device__ __forceinline__ u64 fmul2(u64 a, u64 b){
    u64 d; asm("mul.rn.f32x2 %0,%1,%2;" : "=l"(d) : "l"(a), "l"(b)); return d;
}
__device__ __forceinline__ u64 fadd2(u64 a, u64 b){
    u64 d; asm("add.rn.f32x2 %0,%1,%2;" : "=l"(d) : "l"(a), "l"(b)); return d;
}
__device__ __forceinline__ float sigmoidf_(float x){ return 1.f/(1.f + __expf(-x)); }

// fast 2^t on FMA/ALU pipes only (no MUFU). t <= 0 expected; clamped at -126.
__device__ __forceinline__ float fexp2(float t){
    t = fmaxf(t, -126.f);
    float z = t + 12582912.f;                       // 1.5*2^23: round-to-int
    int   e = __float_as_int(z) - 0x4B400000;       // = rint(t)
    float f = t - (z - 12582912.f);                 // f in [-0.5, 0.5]
    float p =              1.3333558146e-3f;
    p = fmaf(p, f, 9.6181291076e-3f);
    p = fmaf(p, f, 5.5504108664e-2f);
    p = fmaf(p, f, 2.4015967793e-1f);
    p = fmaf(p, f, 6.9314718056e-1f);
    p = fmaf(p, f, 1.0f);
    return __int_as_float(__float_as_int(p) + (e << 23));
}

// ------------------------- tf32 warp mma (baseline PTX, sm_103-legal) -------
__device__ __forceinline__ void mma_tf32(float* d, u32 a0, u32 a1, u32 a2, u32 a3,
                                         u32 b0, u32 b1){
    asm volatile(
        "mma.sync.aligned.m16n8k8.row.col.f32.tf32.tf32.f32 "
        "{%0,%1,%2,%3}, {%4,%5,%6,%7}, {%8,%9}, {%0,%1,%2,%3};"
        : "+f"(d[0]), "+f"(d[1]), "+f"(d[2]), "+f"(d[3])
        : "r"(a0), "r"(a1), "r"(a2), "r"(a3), "r"(b0), "r"(b1));
}

// ------------------------- kernel 1: LayerNorm(a) + weight fold (block 96) --
__global__ void k_lnaprep(const float* __restrict__ a, const float* __restrict__ w,
                          const float* __restrict__ b,
                          const float* __restrict__ lnzw, const float* __restrict__ lnzb,
                          const float* __restrict__ Wz){
    if(blockIdx.x == 96){
        __shared__ float sw[128][17];
        __shared__ float sb2[128][17];
        int c = threadIdx.x;
        if(c < 128){
            float w2 = lnzw[c], bb = lnzb[c];
            #pragma unroll
            for(int h=0; h<16; h++){
                float wz = Wz[c*16 + h];
                float wp = w2*wz;
                u32 tf; asm("cvt.rna.tf32.f32 %0, %1;" : "=r"(tf) : "f"(wp));
                float wpr = __uint_as_float(tf);
                g_Wpt[h*128 + c] = wpr;
                sw[c][h] = wpr;
                sb2[c][h] = bb*wz;
            }
        }
        __syncthreads();
        if(c < 16){
            float s = 0.f, cb = 0.f;
            for(int j=0; j<128; j++){ s += sw[j][c]; cb += sb2[j][c]; }
            g_S[c] = s; g_Cb[c] = cb;
        }
        return;
    }
    int warp = threadIdx.x >> 5, lane = threadIdx.x & 31;
    int row = blockIdx.x*8 + warp;
    const float* ar = a + (size_t)row*CC;
    float v[12]; float s = 0.f, ss = 0.f;
    #pragma unroll
    for(int r=0; r<12; r++){ v[r] = ar[lane + r*32]; s += v[r]; ss += v[r]*v[r]; }
    #pragma unroll
    for(int o=16; o; o>>=1){ s += __shfl_xor_sync(~0u, s, o); ss += __shfl_xor_sync(~0u, ss, o); }
    float mu = s * (1.f/CC);
    float rs = rsqrtf(ss*(1.f/CC) - mu*mu + EPSV);
    float* dr = g_an + (size_t)row*CC;
    #pragma unroll
    for(int r=0; r<12; r++){
        int cc = lane + r*32;
        dr[cc] = (v[r]-mu)*rs*w[cc] + b[cc];
    }
}

// ------------------------- kernel 2: QKVG projections (576 blocks) ----------
__global__ void __launch_bounds__(128) k_proj(const float* __restrict__ Wq,
                                              const float* __restrict__ Wk2,
                                              const float* __restrict__ Wv2,
                                              const float* __restrict__ Wg2,
                                              const float* __restrict__ bg){
    __shared__ __align__(16) float As[64*36];
    __shared__ __align__(16) float Bs[32*36];
    int t = threadIdx.x;
    int n0 = blockIdx.x*32, m0 = blockIdx.y*64, zz = blockIdx.z;
    const float* W = (zz==0) ? Wq : (zz==1) ? Wk2 : (zz==2) ? Wv2 : Wg2;
    float* Cd = (zz==0) ? g_q : (zz==1) ? g_k : (zz==2) ? g_v : g_g;
    u64 acc[4][2];
    #pragma unroll
    for(int r=0;r<4;r++){ acc[r][0]=0; acc[r][1]=0; }
    int tm = t & 15, tn = t >> 4;

    for(int k0=0; k0<CC; k0+=32){
        __syncthreads();
        #pragma unroll
        for(int r=0; r<4; r++){
            int idx = t + 128*r;
            int row = idx >> 3, c4 = idx & 7;
            float4 av = *(const float4*)&g_an[(size_t)(m0+row)*CC + k0 + c4*4];
            *(float4*)&As[row*36 + c4*4] = av;
        }
        #pragma unroll
        for(int r=0; r<2; r++){
            int idx = t + 128*r;
            int kr = idx >> 3, n4 = idx & 7;
            float4 bv = *(const float4*)&W[(size_t)(k0+kr)*CC + n0 + n4*4];
            *(float4*)&Bs[kr*36 + n4*4] = bv;
        }
        __syncthreads();
        #pragma unroll 8
        for(int kk=0; kk<32; kk++){
            u64 b0 = *(const u64*)&Bs[kk*36 + tn*4 + 0];
            u64 b1 = *(const u64*)&Bs[kk*36 + tn*4 + 2];
            #pragma unroll
            for(int r=0; r<4; r++){
                float a = As[(tm + 16*r)*36 + kk];
                u64 a2 = pk2(a, a);
                acc[r][0] = ffma2(a2, b0, acc[r][0]);
                acc[r][1] = ffma2(a2, b1, acc[r][1]);
            }
        }
    }
    #pragma unroll
    for(int r=0; r<4; r++){
        int m = m0 + tm + 16*r;
        #pragma unroll
        for(int p=0; p<2; p++){
            int n = n0 + tn*4 + 2*p;
            float2 vv = up2(acc[r][p]);
            if(zz == 3){ vv.x += bg[n]; vv.y += bg[n+1]; }
            *(float2*)&Cd[(size_t)m*CC + n] = vv;
        }
    }
}

// ------------------------- kernel 3: pair bias, tf32 mma + double buffer ----
__global__ void __launch_bounds__(128) k_bias(const float* __restrict__ z){
    __shared__ __align__(16) float wt[16*132];       // 8.4KB [h][c]
    __shared__ __align__(16) float zs[2][128*36];    // 2 x 18.4KB ping-pong
    __shared__ float smu[128], srs[128], sS[16], sCb[16];
    int t = threadIdx.x;
    int warp = t >> 5, lane = t & 31, g = lane >> 2, tig = lane & 3;
    int i = blockIdx.y, j0 = blockIdx.x*128;

    #pragma unroll
    for(int r=0; r<4; r++){
        int idx = t + 128*r;
        int h = idx >> 5, cq = idx & 31;
        *(float4*)&wt[h*132 + cq*4] = *(const float4*)&g_Wpt[h*128 + cq*4];
    }
    if(t < 16){ sS[t] = g_S[t]; sCb[t] = g_Cb[t]; }

    const float* zbase = z + ((size_t)i*NN + j0)*CZd;
    float sum = 0.f, ssq = 0.f;
    float d[2][2][4] = {};

    #pragma unroll
    for(int r=0; r<8; r++){
        int idx = t + 128*r;
        int j = idx >> 3, cq = idx & 7;
        *(float4*)&zs[0][j*36 + cq*4] = *(const float4*)(zbase + (size_t)j*CZd + cq*4);
    }
    __syncthreads();

    #pragma unroll
    for(int p=0; p<4; p++){
        if(p < 3){
            #pragma unroll
            for(int r=0; r<8; r++){
                int idx = t + 128*r;
                int j = idx >> 3, cq = idx & 7;
                *(float4*)&zs[(p+1)&1][j*36 + cq*4] =
                    *(const float4*)(zbase + (size_t)j*CZd + (p+1)*32 + cq*4);
            }
        }
        const float* zb = zs[p&1];
        #pragma unroll
        for(int c=0; c<8; c++){
            float4 v = *(const float4*)&zb[t*36 + c*4];
            sum += (v.x + v.y) + (v.z + v.w);
            ssq = fmaf(v.x, v.x, ssq); ssq = fmaf(v.y, v.y, ssq);
            ssq = fmaf(v.z, v.z, ssq); ssq = fmaf(v.w, v.w, ssq);
        }
        #pragma unroll
        for(int kt=0; kt<4; kt++){
            int kb = kt*8;
            int kw = p*32 + kb;
            u32 b00 = *(const u32*)&wt[g*132     + kw + tig];
            u32 b01 = *(const u32*)&wt[g*132     + kw + tig + 4];
            u32 b10 = *(const u32*)&wt[(8+g)*132 + kw + tig];
            u32 b11 = *(const u32*)&wt[(8+g)*132 + kw + tig + 4];
            #pragma unroll
            for(int mt=0; mt<2; mt++){
                int rb = warp*32 + mt*16;
                u32 a0 = *(const u32*)&zb[(rb+g)*36   + kb + tig];
                u32 a1 = *(const u32*)&zb[(rb+g+8)*36 + kb + tig];
                u32 a2 = *(const u32*)&zb[(rb+g)*36   + kb + tig + 4];
                u32 a3 = *(const u32*)&zb[(rb+g+8)*36 + kb + tig + 4];
                mma_tf32(d[mt][0], a0, a1, a2, a3, b00, b01);
                mma_tf32(d[mt][1], a0, a1, a2, a3, b10, b11);
            }
        }
        __syncthreads();
    }
    float mu = sum * (1.f/128.f);
    float rs = rsqrtf(ssq*(1.f/128.f) - mu*mu + EPSV);
    smu[t] = mu; srs[t] = rs;
    __syncthreads();

    __half* sh = (__half*)&zs[0][0];     // [h][128 j]
    #pragma unroll
    for(int mt=0; mt<2; mt++){
        int rA = warp*32 + mt*16 + g;
        int rB = rA + 8;
        float muA = smu[rA], rsA = srs[rA];
        float muB = smu[rB], rsB = srs[rB];
        #pragma unroll
        for(int nt=0; nt<2; nt++){
            int h0 = nt*8 + 2*tig, h1 = h0 + 1;
            sh[h0*128 + rA] = __float2half(rsA*(d[mt][nt][0] - muA*sS[h0]) + sCb[h0]);
            sh[h1*128 + rA] = __float2half(rsA*(d[mt][nt][1] - muA*sS[h1]) + sCb[h1]);
            sh[h0*128 + rB] = __float2half(rsB*(d[mt][nt][2] - muB*sS[h0]) + sCb[h0]);
            sh[h1*128 + rB] = __float2half(rsB*(d[mt][nt][3] - muB*sS[h1]) + sCb[h1]);
        }
    }
    __syncthreads();
    const u32* shp = (const u32*)sh;
    #pragma unroll
    for(int r=0; r<8; r++){
        int lin = r*128 + t;
        int h = lin >> 6, j2 = lin & 63;
        *(u32*)&g_bias[(size_t)h*NP + (size_t)i*NN + j0 + 2*j2] = shp[h*64 + j2];
    }
}

// ------------------------- kernel 4: attention, mma QK^T + MUFU-free softmax
// grid (24, 16). 256 threads, 3 blocks/SM. Base-2 domain: log2(e) folded into
// q scale and bias/mask staging; exp via fexp2 (FMA/ALU only).
__global__ void __launch_bounds__(256, 3) k_attn(const float* __restrict__ mask){
    __shared__ __align__(16) float qs[32*28];
    __shared__ __align__(16) float ks[64*28];
    __shared__ __align__(16) float vs[64*28];
    __shared__ float sbf[32*64];
    __shared__ float sraw[32*68];
    __shared__ float smb[NN];
    int t = threadIdx.x;
    int h = blockIdx.y, q0 = blockIdx.x*32;
    const float scale = 0.20412414523193154f * L2E;   // 24^-0.5 * log2(e)
    int warp = t >> 5, lane = t & 31, g = lane >> 2, tig = lane & 3;
    int wm = warp >> 2, wn = warp & 3;

    for(int idx=t; idx<32*24; idx+=256){
        int qq = idx/24, c = idx - qq*24;
        qs[qq*28 + c] = g_q[(size_t)(q0+qq)*CC + h*CHD + c] * scale;
    }
    for(int idx=t; idx<NN; idx+=256) smb[idx] = (INFV*L2E)*(mask[idx] - 1.f);
    __syncthreads();

    int qq = t >> 3, k8 = t & 7;
    float mx = -1e30f, l = 0.f;
    u64 acc[12];
    #pragma unroll
    for(int i2=0; i2<12; i2++) acc[i2] = 0ull;
    const size_t hNP = (size_t)h*NP;
    int aR  = (wm*16 + g)*28, aR8 = (wm*16 + 8 + g)*28;
    int bR  = (wn*16 + g)*28, bR8 = (wn*16 + 8 + g)*28;

    for(int kt0=0; kt0<NN; kt0+=64){
        __syncthreads();
        for(int idx=t; idx<64*24; idx+=256){
            int kk = idx/24, c = idx - kk*24;
            ks[kk*28 + c] = g_k[(size_t)(kt0+kk)*CC + h*CHD + c];
            vs[kk*28 + c] = g_v[(size_t)(kt0+kk)*CC + h*CHD + c];
        }
        #pragma unroll
        for(int r=0; r<4; r++){
            int idx = t + 256*r;
            int q = idx >> 5, k2 = idx & 31;
            u32 pv = *(const u32*)&g_bias[hNP + (size_t)(q0+q)*NN + kt0 + 2*k2];
            __half2 hh = *(__half2*)&pv;
            float2 fv = __half22float2(hh);
            sbf[q*64 + 2*k2]     = fmaf(fv.x, L2E, smb[kt0 + 2*k2]);
            sbf[q*64 + 2*k2 + 1] = fmaf(fv.y, L2E, smb[kt0 + 2*k2 + 1]);
        }
        __syncthreads();

        // mma score phase
        float d0[4] = {0.f,0.f,0.f,0.f};
        float d1[4] = {0.f,0.f,0.f,0.f};
        #pragma unroll
        for(int kt=0; kt<3; kt++){
            int kb = kt*8;
            u32 a0 = *(const u32*)&qs[aR  + kb + tig];
            u32 a1 = *(const u32*)&qs[aR8 + kb + tig];
            u32 a2 = *(const u32*)&qs[aR  + kb + tig + 4];
            u32 a3 = *(const u32*)&qs[aR8 + kb + tig + 4];
            u32 b00 = *(const u32*)&ks[bR  + kb + tig];
            u32 b01 = *(const u32*)&ks[bR  + kb + tig + 4];
            u32 b10 = *(const u32*)&ks[bR8 + kb + tig];
            u32 b11 = *(const u32*)&ks[bR8 + kb + tig + 4];
            mma_tf32(d0, a0, a1, a2, a3, b00, b01);
            mma_tf32(d1, a0, a1, a2, a3, b10, b11);
        }
        {
            int r0 = wm*16 + g, c0 = wn*16 + 2*tig;
            sraw[r0*68 + c0]         = d0[0];
            sraw[r0*68 + c0 + 1]     = d0[1];
            sraw[(r0+8)*68 + c0]     = d0[2];
            sraw[(r0+8)*68 + c0 + 1] = d0[3];
            sraw[r0*68 + c0 + 8]     = d1[0];
            sraw[r0*68 + c0 + 9]     = d1[1];
            sraw[(r0+8)*68 + c0 + 8] = d1[2];
            sraw[(r0+8)*68 + c0 + 9] = d1[3];
        }
        __syncthreads();

        // scalar phase: base-2 online softmax + PV (no MUFU)
        float sarr[8];
        #pragma unroll
        for(int ii=0; ii<8; ii++){
            int kk = k8 + ii*8;
            sarr[ii] = sraw[qq*68 + kk] + sbf[qq*64 + kk];
        }
        float tmax = sarr[0];
        #pragma unroll
        for(int ii=1; ii<8; ii++) tmax = fmaxf(tmax, sarr[ii]);
        if(tmax > mx){
            float f = fexp2(mx - tmax);
            l *= f;
            u64 f2 = pk2(f, f);
            #pragma unroll
            for(int i2=0; i2<12; i2++) acc[i2] = fmul2(acc[i2], f2);
            mx = tmax;
        }
        #pragma unroll
        for(int ii=0; ii<8; ii++){
            int kk = k8 + ii*8;
            float e = fexp2(sarr[ii] - mx);
            l += e;
            u64 e2 = pk2(e, e);
            #pragma unroll
            for(int i4=0; i4<6; i4++){
                float4 vv = *(const float4*)&vs[kk*28 + 4*i4];
                acc[2*i4]   = ffma2(pk2(vv.x, vv.y), e2, acc[2*i4]);
                acc[2*i4+1] = ffma2(pk2(vv.z, vv.w), e2, acc[2*i4+1]);
            }
        }
    }
    // merge the 8 lanes that share a q (base-2 factors)
    #pragma unroll
    for(int off=1; off<8; off<<=1){
        float om = __shfl_xor_sync(~0u, mx, off);
        float ol = __shfl_xor_sync(~0u, l,  off);
        float nm = fmaxf(mx, om);
        float fs = fexp2(mx - nm), fo = fexp2(om - nm);
        l = l*fs + ol*fo;
        u64 fs2 = pk2(fs, fs), fo2 = pk2(fo, fo);
        #pragma unroll
        for(int i2=0; i2<12; i2++){
            float2 av = up2(acc[i2]);
            float ox = __shfl_xor_sync(~0u, av.x, off);
            float oy = __shfl_xor_sync(~0u, av.y, off);
            acc[i2] = fadd2(fmul2(acc[i2], fs2), fmul2(pk2(ox, oy), fo2));
        }
        mx = nm;
    }
    if(k8 == 0){
        float inv = 1.f / l;
        u64 iv = pk2(inv, inv);
        float* op = g_o + (size_t)(q0+qq)*CC + h*CHD;
        #pragma unroll
        for(int i2=0; i2<12; i2++){
            float2 vv = up2(fmul2(acc[i2], iv));
            *(float2*)&op[2*i2] = vv;
        }
    }
}

// ------------------------- kernel 5: gated output projection (144 blocks) ---
__global__ void __launch_bounds__(128) k_oproj(const float* __restrict__ Wo,
                                               const float* __restrict__ bo,
                                               float* __restrict__ out){
    __shared__ __align__(16) float As[64*36];
    __shared__ __align__(16) float Bs[32*36];
    int t = threadIdx.x;
    int n0 = blockIdx.x*32, m0 = blockIdx.y*64;
    u64 acc[4][2];
    #pragma unroll
    for(int r=0;r<4;r++){ acc[r][0]=0; acc[r][1]=0; }
    int tm = t & 15, tn = t >> 4;

    for(int k0=0; k0<CC; k0+=32){
        __syncthreads();
        #pragma unroll
        for(int r=0; r<4; r++){
            int idx = t + 128*r;
            int row = idx >> 3, c4 = idx & 7;
            size_t aoff = (size_t)(m0+row)*CC + k0 + c4*4;
            float4 ov = *(const float4*)&g_o[aoff];
            float4 gv = *(const float4*)&g_g[aoff];
            float4 av;
            av.x = ov.x * sigmoidf_(gv.x);
            av.y = ov.y * sigmoidf_(gv.y);
            av.z = ov.z * sigmoidf_(gv.z);
            av.w = ov.w * sigmoidf_(gv.w);
            *(float4*)&As[row*36 + c4*4] = av;
        }
        #pragma unroll
        for(int r=0; r<2; r++){
            int idx = t + 128*r;
            int kr = idx >> 3, n4 = idx & 7;
            float4 bv = *(const float4*)&Wo[(size_t)(k0+kr)*CC + n0 + n4*4];
            *(float4*)&Bs[kr*36 + n4*4] = bv;
        }
        __syncthreads();
        #pragma unroll 8
        for(int kk=0; kk<32; kk++){
            u64 b0 = *(const u64*)&Bs[kk*36 + tn*4 + 0];
            u64 b1 = *(const u64*)&Bs[kk*36 + tn*4 + 2];
            #pragma unroll
            for(int r=0; r<4; r++){
                float av = As[(tm + 16*r)*36 + kk];
                u64 a2 = pk2(av, av);
                acc[r][0] = ffma2(a2, b0, acc[r][0]);
                acc[r][1] = ffma2(a2, b1, acc[r][1]);
            }
        }
    }
    #pragma unroll
    for(int r=0; r<4; r++){
        int m = m0 + tm + 16*r;
        #pragma unroll
        for(int p=0; p<2; p++){
            int n = n0 + tn*4 + 2*p;
            float2 vv = up2(acc[r][p]);
            vv.x += bo[n]; vv.y += bo[n+1];
            *(float2*)&out[(size_t)m*CC + n] = vv;
        }
    }
}

// ------------------------- launch (serial; attn at profiled idx 3) ----------
extern "C" void kernel_launch(void* const* d_in, const int* in_sizes, int n_in,
                              void* d_out, int out_size){
    const float* a     = (const float*)d_in[0];
    const float* z     = (const float*)d_in[1];
    const float* mask  = (const float*)d_in[2];
    const float* lnaw  = (const float*)d_in[3];
    const float* lnab  = (const float*)d_in[4];
    const float* lnzw  = (const float*)d_in[5];
    const float* lnzb  = (const float*)d_in[6];
    const float* Wz    = (const float*)d_in[7];
    const float* Wq    = (const float*)d_in[8];
    const float* Wk    = (const float*)d_in[9];
    const float* Wv    = (const float*)d_in[10];
    const float* Wg    = (const float*)d_in[11];
    const float* bg    = (const float*)d_in[12];
    const float* Wo    = (const float*)d_in[13];
    const float* bo    = (const float*)d_in[14];
    float* out = (float*)d_out;

    k_lnaprep<<<97, 256>>>(a, lnaw, lnab, lnzw, lnzb, Wz);               // 0
    k_proj<<<dim3(12, 12, 4), 128>>>(Wq, Wk, Wv, Wg, bg);                // 1
    k_bias<<<dim3(6, 768), 128>>>(z);                                    // 2
    k_attn<<<dim3(24, 16), 256>>>(mask);                                 // 3 (profiled)
    k_oproj<<<dim3(12, 12), 128>>>(Wo, bo, out);                         // 4
}

// round 16
// speedup vs baseline: 1.0373x; 1.0299x over previous
#include <cuda_runtime.h>
#include <cuda_fp16.h>

#define NN 768
#define CC 384
#define CZd 128
#define HHd 16
#define CHD 24
#define NP (NN*NN)
#define INFV 1e9f
#define EPSV 1e-5f
#define L2E 1.4426950408889634f

typedef unsigned long long u64;
typedef unsigned int u32;

// ------------------------- device scratch (no runtime alloc) ----------------
__device__ float g_an[NN*CC];
__device__ float g_q[NN*CC];
__device__ float g_k[NN*CC];
__device__ float g_v[NN*CC];
__device__ float g_g[NN*CC];
__device__ float g_o[NN*CC];
__device__ float g_Wpt[16*128];        // tf32-rounded Wp^T : [h][c]
__device__ float g_S[HHd];
__device__ float g_Cb[HHd];
__device__ __half g_bias[(size_t)HHd*NP];   // [h][i*768 + j]

// ------------------------- packed f32x2 helpers (sm_103a) -------------------
__device__ __forceinline__ u64 pk2(float x, float y){
    u64 r; asm("mov.b64 %0,{%1,%2};" : "=l"(r) : "r"(__float_as_uint(x)), "r"(__float_as_uint(y))); return r;
}
__device__ __forceinline__ float2 up2(u64 v){
    u32 a,b; asm("mov.b64 {%0,%1},%2;" : "=r"(a), "=r"(b) : "l"(v));
    return make_float2(__uint_as_float(a), __uint_as_float(b));
}
__device__ __forceinline__ u64 ffma2(u64 a, u64 b, u64 c){
    u64 d; asm("fma.rn.f32x2 %0,%1,%2,%3;" : "=l"(d) : "l"(a), "l"(b), "l"(c)); return d;
}
__device__ __forceinline__ u64 fmul2(u64 a, u64 b){
    u64 d; asm("mul.rn.f32x2 %0,%1,%2;" : "=l"(d) : "l"(a), "l"(b)); return d;
}
__device__ __forceinline__ u64 fadd2(u64 a, u64 b){
    u64 d; asm("add.rn.f32x2 %0,%1,%2;" : "=l"(d) : "l"(a), "l"(b)); return d;
}
__device__ __forceinline__ float sigmoidf_(float x){ return 1.f/(1.f + __expf(-x)); }

// fast 2^t on FMA/ALU pipes only. t <= 0 expected; clamped at -126.
__device__ __forceinline__ float fexp2(float t){
    t = fmaxf(t, -126.f);
    float z = t + 12582912.f;                       // 1.5*2^23: round-to-int
    int   e = __float_as_int(z) - 0x4B400000;       // = rint(t)
    float f = t - (z - 12582912.f);                 // f in [-0.5, 0.5]
    float p =              1.3333558146e-3f;
    p = fmaf(p, f, 9.6181291076e-3f);
    p = fmaf(p, f, 5.5504108664e-2f);
    p = fmaf(p, f, 2.4015967793e-1f);
    p = fmaf(p, f, 6.9314718056e-1f);
    p = fmaf(p, f, 1.0f);
    return __int_as_float(__float_as_int(p) + (e << 23));
}

// ------------------------- tf32 warp mma (baseline PTX, sm_103-legal) -------
__device__ __forceinline__ void mma_tf32(float* d, u32 a0, u32 a1, u32 a2, u32 a3,
                                         u32 b0, u32 b1){
    asm volatile(
        "mma.sync.aligned.m16n8k8.row.col.f32.tf32.tf32.f32 "
        "{%0,%1,%2,%3}, {%4,%5,%6,%7}, {%8,%9}, {%0,%1,%2,%3};"
        : "+f"(d[0]), "+f"(d[1]), "+f"(d[2]), "+f"(d[3])
        : "r"(a0), "r"(a1), "r"(a2), "r"(a3), "r"(b0), "r"(b1));
}

// ------------------------- kernel 1: LayerNorm(a) + weight fold (block 96) --
__global__ void k_lnaprep(const float* __restrict__ a, const float* __restrict__ w,
                          const float* __restrict__ b,
                          const float* __restrict__ lnzw, const float* __restrict__ lnzb,
                          const float* __restrict__ Wz){
    if(blockIdx.x == 96){
        __shared__ float sw[128][17];
        __shared__ float sb2[128][17];
        int c = threadIdx.x;
        if(c < 128){
            float w2 = lnzw[c], bb = lnzb[c];
            #pragma unroll
            for(int h=0; h<16; h++){
                float wz = Wz[c*16 + h];
                float wp = w2*wz;
                u32 tf; asm("cvt.rna.tf32.f32 %0, %1;" : "=r"(tf) : "f"(wp));
                float wpr = __uint_as_float(tf);
                g_Wpt[h*128 + c] = wpr;
                sw[c][h] = wpr;
                sb2[c][h] = bb*wz;
            }
        }
        __syncthreads();
        if(c < 16){
            float s = 0.f, cb = 0.f;
            for(int j=0; j<128; j++){ s += sw[j][c]; cb += sb2[j][c]; }
            g_S[c] = s; g_Cb[c] = cb;
        }
        return;
    }
    int warp = threadIdx.x >> 5, lane = threadIdx.x & 31;
    int row = blockIdx.x*8 + warp;
    const float* ar = a + (size_t)row*CC;
    float v[12]; float s = 0.f, ss = 0.f;
    #pragma unroll
    for(int r=0; r<12; r++){ v[r] = ar[lane + r*32]; s += v[r]; ss += v[r]*v[r]; }
    #pragma unroll
    for(int o=16; o; o>>=1){ s += __shfl_xor_sync(~0u, s, o); ss += __shfl_xor_sync(~0u, ss, o); }
    float mu = s * (1.f/CC);
    float rs = rsqrtf(ss*(1.f/CC) - mu*mu + EPSV);
    float* dr = g_an + (size_t)row*CC;
    #pragma unroll
    for(int r=0; r<12; r++){
        int cc = lane + r*32;
        dr[cc] = (v[r]-mu)*rs*w[cc] + b[cc];
    }
}

// ------------------------- kernel 2: QKVG projections (576 blocks) ----------
__global__ void __launch_bounds__(128) k_proj(const float* __restrict__ Wq,
                                              const float* __restrict__ Wk2,
                                              const float* __restrict__ Wv2,
                                              const float* __restrict__ Wg2,
                                              const float* __restrict__ bg){
    __shared__ __align__(16) float As[64*36];
    __shared__ __align__(16) float Bs[32*36];
    int t = threadIdx.x;
    int n0 = blockIdx.x*32, m0 = blockIdx.y*64, zz = blockIdx.z;
    const float* W = (zz==0) ? Wq : (zz==1) ? Wk2 : (zz==2) ? Wv2 : Wg2;
    float* Cd = (zz==0) ? g_q : (zz==1) ? g_k : (zz==2) ? g_v : g_g;
    u64 acc[4][2];
    #pragma unroll
    for(int r=0;r<4;r++){ acc[r][0]=0; acc[r][1]=0; }
    int tm = t & 15, tn = t >> 4;

    for(int k0=0; k0<CC; k0+=32){
        __syncthreads();
        #pragma unroll
        for(int r=0; r<4; r++){
            int idx = t + 128*r;
            int row = idx >> 3, c4 = idx & 7;
            float4 av = *(const float4*)&g_an[(size_t)(m0+row)*CC + k0 + c4*4];
            *(float4*)&As[row*36 + c4*4] = av;
        }
        #pragma unroll
        for(int r=0; r<2; r++){
            int idx = t + 128*r;
            int kr = idx >> 3, n4 = idx & 7;
            float4 bv = *(const float4*)&W[(size_t)(k0+kr)*CC + n0 + n4*4];
            *(float4*)&Bs[kr*36 + n4*4] = bv;
        }
        __syncthreads();
        #pragma unroll 8
        for(int kk=0; kk<32; kk++){
            u64 b0 = *(const u64*)&Bs[kk*36 + tn*4 + 0];
            u64 b1 = *(const u64*)&Bs[kk*36 + tn*4 + 2];
            #pragma unroll
            for(int r=0; r<4; r++){
                float a = As[(tm + 16*r)*36 + kk];
                u64 a2 = pk2(a, a);
                acc[r][0] = ffma2(a2, b0, acc[r][0]);
                acc[r][1] = ffma2(a2, b1, acc[r][1]);
            }
        }
    }
    #pragma unroll
    for(int r=0; r<4; r++){
        int m = m0 + tm + 16*r;
        #pragma unroll
        for(int p=0; p<2; p++){
            int n = n0 + tn*4 + 2*p;
            float2 vv = up2(acc[r][p]);
            if(zz == 3){ vv.x += bg[n]; vv.y += bg[n+1]; }
            *(float2*)&Cd[(size_t)m*CC + n] = vv;
        }
    }
}

// ------------------------- kernel 3: pair bias, tf32 mma + double buffer ----
__global__ void __launch_bounds__(128) k_bias(const float* __restrict__ z){
    __shared__ __align__(16) float wt[16*132];       // 8.4KB [h][c]
    __shared__ __align__(16) float zs[2][128*36];    // 2 x 18.4KB ping-pong
    __shared__ float smu[128], srs[128], sS[16], sCb[16];
    int t = threadIdx.x;
    int warp = t >> 5, lane = t & 31, g = lane >> 2, tig = lane & 3;
    int i = blockIdx.y, j0 = blockIdx.x*128;

    #pragma unroll
    for(int r=0; r<4; r++){
        int idx = t + 128*r;
        int h = idx >> 5, cq = idx & 31;
        *(float4*)&wt[h*132 + cq*4] = *(const float4*)&g_Wpt[h*128 + cq*4];
    }
    if(t < 16){ sS[t] = g_S[t]; sCb[t] = g_Cb[t]; }

    const float* zbase = z + ((size_t)i*NN + j0)*CZd;
    float sum = 0.f, ssq = 0.f;
    float d[2][2][4] = {};

    #pragma unroll
    for(int r=0; r<8; r++){
        int idx = t + 128*r;
        int j = idx >> 3, cq = idx & 7;
        *(float4*)&zs[0][j*36 + cq*4] = *(const float4*)(zbase + (size_t)j*CZd + cq*4);
    }
    __syncthreads();

    #pragma unroll
    for(int p=0; p<4; p++){
        if(p < 3){
            #pragma unroll
            for(int r=0; r<8; r++){
                int idx = t + 128*r;
                int j = idx >> 3, cq = idx & 7;
                *(float4*)&zs[(p+1)&1][j*36 + cq*4] =
                    *(const float4*)(zbase + (size_t)j*CZd + (p+1)*32 + cq*4);
            }
        }
        const float* zb = zs[p&1];
        #pragma unroll
        for(int c=0; c<8; c++){
            float4 v = *(const float4*)&zb[t*36 + c*4];
            sum += (v.x + v.y) + (v.z + v.w);
            ssq = fmaf(v.x, v.x, ssq); ssq = fmaf(v.y, v.y, ssq);
            ssq = fmaf(v.z, v.z, ssq); ssq = fmaf(v.w, v.w, ssq);
        }
        #pragma unroll
        for(int kt=0; kt<4; kt++){
            int kb = kt*8;
            int kw = p*32 + kb;
            u32 b00 = *(const u32*)&wt[g*132     + kw + tig];
            u32 b01 = *(const u32*)&wt[g*132     + kw + tig + 4];
            u32 b10 = *(const u32*)&wt[(8+g)*132 + kw + tig];
            u32 b11 = *(const u32*)&wt[(8+g)*132 + kw + tig + 4];
            #pragma unroll
            for(int mt=0; mt<2; mt++){
                int rb = warp*32 + mt*16;
                u32 a0 = *(const u32*)&zb[(rb+g)*36   + kb + tig];
                u32 a1 = *(const u32*)&zb[(rb+g+8)*36 + kb + tig];
                u32 a2 = *(const u32*)&zb[(rb+g)*36   + kb + tig + 4];
                u32 a3 = *(const u32*)&zb[(rb+g+8)*36 + kb + tig + 4];
                mma_tf32(d[mt][0], a0, a1, a2, a3, b00, b01);
                mma_tf32(d[mt][1], a0, a1, a2, a3, b10, b11);
            }
        }
        __syncthreads();
    }
    float mu = sum * (1.f/128.f);
    float rs = rsqrtf(ssq*(1.f/128.f) - mu*mu + EPSV);
    smu[t] = mu; srs[t] = rs;
    __syncthreads();

    __half* sh = (__half*)&zs[0][0];     // [h][128 j]
    #pragma unroll
    for(int mt=0; mt<2; mt++){
        int rA = warp*32 + mt*16 + g;
        int rB = rA + 8;
        float muA = smu[rA], rsA = srs[rA];
        float muB = smu[rB], rsB = srs[rB];
        #pragma unroll
        for(int nt=0; nt<2; nt++){
            int h0 = nt*8 + 2*tig, h1 = h0 + 1;
            sh[h0*128 + rA] = __float2half(rsA*(d[mt][nt][0] - muA*sS[h0]) + sCb[h0]);
            sh[h1*128 + rA] = __float2half(rsA*(d[mt][nt][1] - muA*sS[h1]) + sCb[h1]);
            sh[h0*128 + rB] = __float2half(rsB*(d[mt][nt][2] - muB*sS[h0]) + sCb[h0]);
            sh[h1*128 + rB] = __float2half(rsB*(d[mt][nt][3] - muB*sS[h1]) + sCb[h1]);
        }
    }
    __syncthreads();
    const u32* shp = (const u32*)sh;
    #pragma unroll
    for(int r=0; r<8; r++){
        int lin = r*128 + t;
        int h = lin >> 6, j2 = lin & 63;
        *(u32*)&g_bias[(size_t)h*NP + (size_t)i*NN + j0 + 2*j2] = shp[h*64 + j2];
    }
}

// ------------------------- kernel 4: attention, full-mma flash --------------
// grid (24, 16). 256 threads. Scores AND PV on tensor pipe; online softmax
// state (mx, l, rescale) per row in smem; P written in place over raw scores.
// Warp w = (wm2 = w>>2, wn2 = w&3) owns O tile rows wm2*16..+16, cols wn2*8..+8
// (cols >= 24 are padding; V transposed+padded to 32 rows of zeros).
__global__ void __launch_bounds__(256) k_attn(const float* __restrict__ mask){
    __shared__ __align__(16) float qs[32*28];
    __shared__ __align__(16) float ks[64*28];
    __shared__ __align__(16) float vst[32*68];   // V^T [c][k], rows 24..31 zero
    __shared__ float sbf[32*64];
    __shared__ float sraw[32*68];                // raw scores -> P (in place)
    __shared__ float smb[NN];
    __shared__ float mxs[32], ls[32], frs[32];
    int t = threadIdx.x;
    int h = blockIdx.y, q0 = blockIdx.x*32;
    const float scale = 0.20412414523193154f * L2E;
    int warp = t >> 5, lane = t & 31, g = lane >> 2, tig = lane & 3;
    int wm = warp >> 2, wn = warp & 3;

    for(int idx=t; idx<32*24; idx+=256){
        int qq = idx/24, c = idx - qq*24;
        qs[qq*28 + c] = g_q[(size_t)(q0+qq)*CC + h*CHD + c] * scale;
    }
    for(int idx=t; idx<NN; idx+=256) smb[idx] = (INFV*L2E)*(mask[idx] - 1.f);
    // zero V^T padding rows 24..31 (written once; staging only touches c<24)
    for(int idx=t; idx<8*68; idx+=256) vst[24*68 + idx] = 0.f;
    if(t < 32){ mxs[t] = -1e30f; ls[t] = 0.f; }
    __syncthreads();

    int qq = t >> 3, k8 = t & 7;
    float od[4] = {0.f, 0.f, 0.f, 0.f};        // PV accumulator fragments
    const size_t hNP = (size_t)h*NP;
    int aR  = (wm*16 + g)*28, aR8 = (wm*16 + 8 + g)*28;
    int bR  = (wn*16 + g)*28, bR8 = (wn*16 + 8 + g)*28;
    int pR  = (wm*16 + g)*68, pR8 = (wm*16 + 8 + g)*68;
    int vR  = (wn*8 + g)*68;

    for(int kt0=0; kt0<NN; kt0+=64){
        __syncthreads();
        for(int idx=t; idx<64*24; idx+=256){
            int kk = idx/24, c = idx - kk*24;
            float kv = g_k[(size_t)(kt0+kk)*CC + h*CHD + c];
            float vv = g_v[(size_t)(kt0+kk)*CC + h*CHD + c];
            ks[kk*28 + c] = kv;
            vst[c*68 + kk] = vv;
        }
        #pragma unroll
        for(int r=0; r<4; r++){
            int idx = t + 256*r;
            int q = idx >> 5, k2 = idx & 31;
            u32 pv = *(const u32*)&g_bias[hNP + (size_t)(q0+q)*NN + kt0 + 2*k2];
            __half2 hh = *(__half2*)&pv;
            float2 fv = __half22float2(hh);
            sbf[q*64 + 2*k2]     = fmaf(fv.x, L2E, smb[kt0 + 2*k2]);
            sbf[q*64 + 2*k2 + 1] = fmaf(fv.y, L2E, smb[kt0 + 2*k2 + 1]);
        }
        __syncthreads();

        // score mma: warp (wm, wn) -> rows wm*16..+16, cols wn*16..+16
        float d0[4] = {0.f,0.f,0.f,0.f};
        float d1[4] = {0.f,0.f,0.f,0.f};
        #pragma unroll
        for(int kt=0; kt<3; kt++){
            int kb = kt*8;
            u32 a0 = *(const u32*)&qs[aR  + kb + tig];
            u32 a1 = *(const u32*)&qs[aR8 + kb + tig];
            u32 a2 = *(const u32*)&qs[aR  + kb + tig + 4];
            u32 a3 = *(const u32*)&qs[aR8 + kb + tig + 4];
            u32 b00 = *(const u32*)&ks[bR  + kb + tig];
            u32 b01 = *(const u32*)&ks[bR  + kb + tig + 4];
            u32 b10 = *(const u32*)&ks[bR8 + kb + tig];
            u32 b11 = *(const u32*)&ks[bR8 + kb + tig + 4];
            mma_tf32(d0, a0, a1, a2, a3, b00, b01);
            mma_tf32(d1, a0, a1, a2, a3, b10, b11);
        }
        {
            int r0 = wm*16 + g, c0 = wn*16 + 2*tig;
            sraw[r0*68 + c0]         = d0[0];
            sraw[r0*68 + c0 + 1]     = d0[1];
            sraw[(r0+8)*68 + c0]     = d0[2];
            sraw[(r0+8)*68 + c0 + 1] = d0[3];
            sraw[r0*68 + c0 + 8]     = d1[0];
            sraw[r0*68 + c0 + 9]     = d1[1];
            sraw[(r0+8)*68 + c0 + 8] = d1[2];
            sraw[(r0+8)*68 + c0 + 9] = d1[3];
        }
        __syncthreads();

        // softmax: row qq, 8 cols per thread; P written in place
        float sarr[8];
        #pragma unroll
        for(int ii=0; ii<8; ii++){
            int kk = k8 + ii*8;
            sarr[ii] = sraw[qq*68 + kk] + sbf[qq*64 + kk];
        }
        float tm2 = sarr[0];
        #pragma unroll
        for(int ii=1; ii<8; ii++) tm2 = fmaxf(tm2, sarr[ii]);
        #pragma unroll
        for(int off=1; off<8; off<<=1) tm2 = fmaxf(tm2, __shfl_xor_sync(~0u, tm2, off));
        float old = mxs[qq];
        float nm = fmaxf(old, tm2);
        float lsum = 0.f;
        #pragma unroll
        for(int ii=0; ii<8; ii++){
            int kk = k8 + ii*8;
            float e = fexp2(sarr[ii] - nm);
            lsum += e;
            sraw[qq*68 + kk] = e;
        }
        #pragma unroll
        for(int off=1; off<8; off<<=1) lsum += __shfl_xor_sync(~0u, lsum, off);
        if(k8 == 0){
            float fr = fexp2(old - nm);
            mxs[qq] = nm;
            ls[qq] = ls[qq]*fr + lsum;
            frs[qq] = fr;
        }
        __syncthreads();

        // PV mma: rescale fragments by per-row factor, then P(32x64) x V^T
        float fr0 = frs[wm*16 + g], fr1 = frs[wm*16 + 8 + g];
        od[0] *= fr0; od[1] *= fr0; od[2] *= fr1; od[3] *= fr1;
        #pragma unroll
        for(int ks8=0; ks8<8; ks8++){
            int kb = ks8*8;
            u32 a0 = *(const u32*)&sraw[pR  + kb + tig];
            u32 a1 = *(const u32*)&sraw[pR8 + kb + tig];
            u32 a2 = *(const u32*)&sraw[pR  + kb + tig + 4];
            u32 a3 = *(const u32*)&sraw[pR8 + kb + tig + 4];
            u32 b0 = *(const u32*)&vst[vR + kb + tig];
            u32 b1 = *(const u32*)&vst[vR + kb + tig + 4];
            mma_tf32(od, a0, a1, a2, a3, b0, b1);
        }
    }
    __syncthreads();

    // normalize + store (cols >= 24 are padding)
    int c0 = wn*8 + 2*tig;
    if(c0 < CHD){
        int r0 = wm*16 + g, r1 = r0 + 8;
        float inv0 = 1.f / ls[r0], inv1 = 1.f / ls[r1];
        float* op0 = g_o + (size_t)(q0+r0)*CC + h*CHD + c0;
        float* op1 = g_o + (size_t)(q0+r1)*CC + h*CHD + c0;
        *(float2*)op0 = make_float2(od[0]*inv0, od[1]*inv0);
        *(float2*)op1 = make_float2(od[2]*inv1, od[3]*inv1);
    }
}

// ------------------------- kernel 5: gated output projection (144 blocks) ---
__global__ void __launch_bounds__(128) k_oproj(const float* __restrict__ Wo,
                                               const float* __restrict__ bo,
                                               float* __restrict__ out){
    __shared__ __align__(16) float As[64*36];
    __shared__ __align__(16) float Bs[32*36];
    int t = threadIdx.x;
    int n0 = blockIdx.x*32, m0 = blockIdx.y*64;
    u64 acc[4][2];
    #pragma unroll
    for(int r=0;r<4;r++){ acc[r][0]=0; acc[r][1]=0; }
    int tm = t & 15, tn = t >> 4;

    for(int k0=0; k0<CC; k0+=32){
        __syncthreads();
        #pragma unroll
        for(int r=0; r<4; r++){
            int idx = t + 128*r;
            int row = idx >> 3, c4 = idx & 7;
            size_t aoff = (size_t)(m0+row)*CC + k0 + c4*4;
            float4 ov = *(const float4*)&g_o[aoff];
            float4 gv = *(const float4*)&g_g[aoff];
            float4 av;
            av.x = ov.x * sigmoidf_(gv.x);
            av.y = ov.y * sigmoidf_(gv.y);
            av.z = ov.z * sigmoidf_(gv.z);
            av.w = ov.w * sigmoidf_(gv.w);
            *(float4*)&As[row*36 + c4*4] = av;
        }
        #pragma unroll
        for(int r=0; r<2; r++){
            int idx = t + 128*r;
            int kr = idx >> 3, n4 = idx & 7;
            float4 bv = *(const float4*)&Wo[(size_t)(k0+kr)*CC + n0 + n4*4];
            *(float4*)&Bs[kr*36 + n4*4] = bv;
        }
        __syncthreads();
        #pragma unroll 8
        for(int kk=0; kk<32; kk++){
            u64 b0 = *(const u64*)&Bs[kk*36 + tn*4 + 0];
            u64 b1 = *(const u64*)&Bs[kk*36 + tn*4 + 2];
            #pragma unroll
            for(int r=0; r<4; r++){
                float av = As[(tm + 16*r)*36 + kk];
                u64 a2 = pk2(av, av);
                acc[r][0] = ffma2(a2, b0, acc[r][0]);
                acc[r][1] = ffma2(a2, b1, acc[r][1]);
            }
        }
    }
    #pragma unroll
    for(int r=0; r<4; r++){
        int m = m0 + tm + 16*r;
        #pragma unroll
        for(int p=0; p<2; p++){
            int n = n0 + tn*4 + 2*p;
            float2 vv = up2(acc[r][p]);
            vv.x += bo[n]; vv.y += bo[n+1];
            *(float2*)&out[(size_t)m*CC + n] = vv;
        }
    }
}

// ------------------------- launch (serial; attn at profiled idx 3) ----------
extern "C" void kernel_launch(void* const* d_in, const int* in_sizes, int n_in,
                              void* d_out, int out_size){
    const float* a     = (const float*)d_in[0];
    const float* z     = (const float*)d_in[1];
    const float* mask  = (const float*)d_in[2];
    const float* lnaw  = (const float*)d_in[3];
    const float* lnab  = (const float*)d_in[4];
    const float* lnzw  = (const float*)d_in[5];
    const float* lnzb  = (const float*)d_in[6];
    const float* Wz    = (const float*)d_in[7];
    const float* Wq    = (const float*)d_in[8];
    const float* Wk    = (const float*)d_in[9];
    const float* Wv    = (const float*)d_in[10];
    const float* Wg    = (const float*)d_in[11];
    const float* bg    = (const float*)d_in[12];
    const float* Wo    = (const float*)d_in[13];
    const float* bo    = (const float*)d_in[14];
    float* out = (float*)d_out;

    k_lnaprep<<<97, 256>>>(a, lnaw, lnab, lnzw, lnzb, Wz);               // 0
    k_proj<<<dim3(12, 12, 4), 128>>>(Wq, Wk, Wv, Wg, bg);                // 1
    k_bias<<<dim3(6, 768), 128>>>(z);                                    // 2
    k_attn<<<dim3(24, 16), 256>>>(mask);                                 // 3 (profiled)
    k_oproj<<<dim3(12, 12), 128>>>(Wo, bo, out);                         // 4
}